// round 14
// baseline (speedup 1.0000x reference)
#include <cuda_runtime.h>
#include <cuda_fp16.h>
#include <cstdint>

#define HWSZ 9216            // 96*96
#define NCH  128
#define NE   8
#define P_TOT 36864          // 4*96*96
#define KFULL 1152           // 128*9
#define NKB   18             // K-blocks of 64, tap-major: k = tap*128 + ci
#define NPART 32
#define PPP   (P_TOT / NPART)   // 1152 pixels per part

typedef unsigned long long ull;

// ---------------- device scratch ----------------
__device__ __half g_xh[(long)P_TOT * NCH];             // x transposed [p][ci], fp16
__device__ __half g_wh[(long)NE * NKB * 128 * 64];     // merged (We+Wsh) B tiles, fp16
__device__ float  g_acc[(long)P_TOT * NCH];            // pixel-major accumulator
__device__ int    g_sel01[P_TOT];
__device__ float2 g_w01[P_TOT];
__device__ int    g_listP[NE * P_TOT];
__device__ float  g_listW[NE * P_TOT];
__device__ int    g_cnt[NE];
__device__ int    g_pcnt[NE * NPART];

// ---------------- smem layout for conv (offsets from 1024-aligned base) -------------
#define SM_SPIX 65536        // 9*128 int
#define SM_PP   70144        // 128 int
#define SM_PW0  70656        // 128 float
#define SMEM_BYTES 72192

// ---------------- PTX helpers ----------------
__device__ __forceinline__ uint32_t smem_u32(const void* p) {
    return (uint32_t)__cvta_generic_to_shared(p);
}
__device__ __forceinline__ void cpa16(uint32_t dst, const void* src, int ssz) {
    asm volatile("cp.async.cg.shared.global [%0], [%1], 16, %2;"
                 :: "r"(dst), "l"(src), "r"(ssz) : "memory");
}
__device__ __forceinline__ void cp_commit() {
    asm volatile("cp.async.commit_group;" ::: "memory");
}
__device__ __forceinline__ void ldm4(uint32_t* r, uint32_t addr) {
    asm volatile("ldmatrix.sync.aligned.m8n8.x4.shared.b16 {%0,%1,%2,%3}, [%4];"
                 : "=r"(r[0]), "=r"(r[1]), "=r"(r[2]), "=r"(r[3]) : "r"(addr));
}
__device__ __forceinline__ void mma16816(float* d, const uint32_t* a, const uint32_t* b) {
    asm volatile("mma.sync.aligned.m16n8k16.row.col.f32.f16.f16.f32 "
                 "{%0,%1,%2,%3}, {%4,%5,%6,%7}, {%8,%9}, {%0,%1,%2,%3};"
                 : "+f"(d[0]), "+f"(d[1]), "+f"(d[2]), "+f"(d[3])
                 : "r"(a[0]), "r"(a[1]), "r"(a[2]), "r"(a[3]),
                   "r"(b[0]), "r"(b[1]));
}
__device__ __forceinline__ ull ffma2(ull a, ull b, ull c) {
    ull d;
    asm("fma.rn.f32x2 %0, %1, %2, %3;" : "=l"(d) : "l"(a), "l"(b), "l"(c));
    return d;
}
__device__ __forceinline__ ull pack2(float lo, float hi) {
    ull d;
    asm("mov.b64 %0, {%1, %2};" : "=l"(d) : "f"(lo), "f"(hi));
    return d;
}
__device__ __forceinline__ ull dup2(float x) {
    ull d;
    asm("mov.b64 %0, {%1, %1};" : "=l"(d) : "f"(x));
    return d;
}
__device__ __forceinline__ float2 unpack2(ull a) {
    float2 r;
    asm("mov.b64 {%0, %1}, %2;" : "=f"(r.x), "=f"(r.y) : "l"(a));
    return r;
}

// ---------------- prep: merged fp16 weights (We + Wsh), pre-swizzled ----------------
__global__ void prep_w(const float* __restrict__ expert_w,
                       const float* __restrict__ shared_w) {
    int idx = blockIdx.x * 256 + threadIdx.x;
    if (idx >= NE * NKB * 128 * 64) return;
    int c   = idx & 63;            // k within 64-block
    int row = (idx >> 6) & 127;    // cout
    int t2  = idx >> 13;
    int kb  = t2 % NKB;
    int e   = t2 / NKB;
    int tap = kb >> 1;
    int ci  = ((kb & 1) << 6) + c;
    float v = expert_w[(((e * NCH + row) * NCH) + ci) * 9 + tap]
            + shared_w[((row * NCH) + ci) * 9 + tap];
    int chunk = c >> 3, within = c & 7;
    int swc = chunk ^ (row & 7);                    // 16B-chunk XOR swizzle
    g_wh[(long)(e * NKB + kb) * 8192 + row * 64 + swc * 8 + within] = __float2half_rn(v);
}

// ---------------- gate (f32x2, 2 pixels/thread) + fused x_t emission ----------------
// block: 128 threads, tile 32 wide x 8 tall. grid (3, 12, 4).
__global__ __launch_bounds__(128) void gate_kernel(
    const float* __restrict__ x, const float* __restrict__ gate_w,
    const float* __restrict__ gate_bias)
{
    __shared__ float xt[8 * 10 * 34];    // 8 ci x (8+2 halo rows) x (32+2 halo cols)
    __shared__ float gwS[NE * 72];       // current chunk: [e][ci*9+t]
    const int tid = threadIdx.x;
    const int tx = tid & 15, ty = tid >> 4;   // pair at w=2tx, row ty
    const int w0 = blockIdx.x * 32, h0 = blockIdx.y * 8, b = blockIdx.z;
    const float* xb = x + (long)b * (NCH * HWSZ);

    ull acc2[NE];
#pragma unroll
    for (int e = 0; e < NE; ++e) acc2[e] = 0ull;

    for (int cc = 0; cc < 16; ++cc) {            // 16 chunks of 8 ci
        __syncthreads();
        for (int i = tid; i < NE * 72; i += 128)
            gwS[i] = gate_w[(i / 72) * KFULL + cc * 72 + (i % 72)];
        for (int i = tid; i < 8 * 340; i += 128) {
            int ci = i / 340; int r = i - ci * 340;
            int ly = r / 34;  int lx = r - ly * 34;
            int gh = h0 + ly - 1, gw = w0 + lx - 1;
            float v = 0.f;
            if ((unsigned)gh < 96u && (unsigned)gw < 96u)
                v = xb[(cc * 8 + ci) * HWSZ + gh * 96 + gw];
            xt[i] = v;
        }
        __syncthreads();
        // emit fp16 x_t for this chunk (inner 32x8 region)
        for (int i = tid; i < 8 * 256; i += 128) {
            int ci = i >> 8; int px = i & 255;
            int row = px >> 5, col = px & 31;
            g_xh[(long)(b * HWSZ + (h0 + row) * 96 + w0 + col) * NCH + cc * 8 + ci] =
                __float2half_rn(xt[ci * 340 + (row + 1) * 34 + col + 1]);
        }
        // packed-pair compute
#pragma unroll
        for (int ci = 0; ci < 8; ++ci) {
#pragma unroll
            for (int r = 0; r < 3; ++r) {
                const float* rowp = &xt[ci * 340 + (ty + r) * 34 + 2 * tx];
                float2 a = *(const float2*)rowp;
                float2 bv = *(const float2*)(rowp + 2);
                ull p0 = pack2(a.x, a.y);
                ull p1 = pack2(a.y, bv.x);
                ull p2 = pack2(bv.x, bv.y);
#pragma unroll
                for (int e = 0; e < NE; ++e) {
                    const float* wp = &gwS[e * 72 + ci * 9 + r * 3];
                    acc2[e] = ffma2(p0, dup2(wp[0]), acc2[e]);
                    acc2[e] = ffma2(p1, dup2(wp[1]), acc2[e]);
                    acc2[e] = ffma2(p2, dup2(wp[2]), acc2[e]);
                }
            }
        }
    }

    float sc[2][NE];
#pragma unroll
    for (int e = 0; e < NE; ++e) {
        float2 v = unpack2(acc2[e]);
        sc[0][e] = v.x; sc[1][e] = v.y;
    }
#pragma unroll
    for (int jx = 0; jx < 2; ++jx) {
        float s[NE];
        float v0 = -1e30f, v1 = -1e30f; int i0 = 0, i1 = 1;
#pragma unroll
        for (int e = 0; e < NE; ++e) {
            float sv = 1.f / (1.f + expf(-sc[jx][e]));
            s[e] = sv;
            float bv = sv + gate_bias[e];
            if (bv > v0)      { v1 = v0; i1 = i0; v0 = bv; i0 = e; }
            else if (bv > v1) { v1 = bv; i1 = e; }
        }
        float s0 = s[i0], s1 = s[i1];
        float mx = fmaxf(s0, s1);
        float e0 = expf(s0 - mx), e1 = expf(s1 - mx);
        float inv = 1.f / (e0 + e1);
        const int p = b * HWSZ + (h0 + ty) * 96 + w0 + 2 * tx + jx;
        g_sel01[p] = i0 | (i1 << 8);
        g_w01[p]   = make_float2(e0 * inv, e1 * inv);
    }
}

// ---------------- parallel deterministic list build --------------------------------
__global__ __launch_bounds__(1024) void list_count() {
    __shared__ int wc[32][8];
    const int part = blockIdx.x;
    const int tid = threadIdx.x, lane = tid & 31, wrp = tid >> 5;
    int cnt = 0;
#pragma unroll
    for (int seg = 0; seg < 2; ++seg) {
        int off = seg * 1024 + tid;
        bool valid = off < PPP;
        int s01 = valid ? g_sel01[part * PPP + off] : 0x0F0F;
#pragma unroll
        for (int e = 0; e < NE; ++e) {
            unsigned m0 = __ballot_sync(0xFFFFFFFFu, (s01 & 255) == e);
            unsigned m1 = __ballot_sync(0xFFFFFFFFu, (s01 >> 8) == e);
            if (lane == e) cnt += __popc(m0) + __popc(m1);
        }
    }
    if (lane < 8) wc[wrp][lane] = cnt;
    __syncthreads();
    if (tid < 8) {
        int a = 0;
#pragma unroll
        for (int w2 = 0; w2 < 32; ++w2) a += wc[w2][tid];
        g_pcnt[tid * NPART + part] = a;
    }
}

__global__ __launch_bounds__(1024) void list_scatter() {
    __shared__ int wsum[32];
    __shared__ int woff[33];
    __shared__ int sbase;
    const int part = blockIdx.x, e = blockIdx.y;
    const int tid = threadIdx.x, lane = tid & 31, wrp = tid >> 5;
    if (tid == 0) {
        int a = 0, tot = 0;
#pragma unroll
        for (int p2 = 0; p2 < NPART; ++p2) {
            int c = g_pcnt[e * NPART + p2];
            if (p2 < part) a += c;
            tot += c;
        }
        sbase = a;
        if (part == 0) g_cnt[e] = tot;
    }
    __syncthreads();
    int base = sbase;
#pragma unroll
    for (int seg = 0; seg < 2; ++seg) {
        int off = seg * 1024 + tid;
        bool valid = off < PPP;
        int p = part * PPP + off;
        int s01 = valid ? g_sel01[p] : 0x0F0F;
        bool f0 = ((s01 & 255) == e), f1 = ((s01 >> 8) == e);
        bool f = f0 || f1;
        unsigned msk = __ballot_sync(0xFFFFFFFFu, f);
        if (lane == 0) wsum[wrp] = __popc(msk);
        __syncthreads();
        if (tid == 0) {
            int a = 0;
#pragma unroll
            for (int w2 = 0; w2 < 32; ++w2) { woff[w2] = a; a += wsum[w2]; }
            woff[32] = a;
        }
        __syncthreads();
        if (f) {
            float2 ww = g_w01[p];
            int pos = base + woff[wrp] + __popc(msk & ((1u << lane) - 1u));
            g_listP[e * P_TOT + pos] = p;
            g_listW[e * P_TOT + pos] = f0 ? ww.x : ww.y;
        }
        base += woff[32];
        __syncthreads();
    }
}

// ---------------- stage fill: gathered A + pre-swizzled B (fp16) --------------------
__device__ __forceinline__ void fill_stage(int tid, uint32_t bb, int kb, int e,
                                           const int* SPIX) {
    const int tap  = kb >> 1;
    const int ci0b = ((kb & 1) << 6) * 2;
    const char* xs = (const char*)g_xh;
    for (int i = tid; i < 1024; i += 256) {         // A: 128 rows x 8 chunks
        int r = i >> 3, cc = i & 7;
        int sp = SPIX[tap * 128 + r];
        uint32_t dst = bb + (uint32_t)(r * 128 + ((cc ^ (r & 7)) << 4));
        const char* src = xs + (long)(sp < 0 ? 0 : sp) * 256 + ci0b + cc * 16;
        cpa16(dst, src, sp < 0 ? 0 : 16);
    }
    const char* ws = (const char*)g_wh;
    const long wb = (long)(e * NKB + kb) * 16384;
    for (int i = tid; i < 1024; i += 256)           // B: plain slab copy
        cpa16(bb + 16384u + (uint32_t)i * 16, ws + wb + (long)i * 16, 16);
    cp_commit();
}

// ---------------- mma.sync conv: one (expert, 128-pixel, 128-cout) tile per CTA -----
__global__ __launch_bounds__(256, 2) void conv_mma()
{
    extern __shared__ char dsm[];
    char* SB = (char*)(((uintptr_t)dsm + 1023) & ~(uintptr_t)1023);
    const uint32_t sb32 = smem_u32(SB);

    int*   SPIX = (int*)(SB + SM_SPIX);
    int*   PP   = (int*)(SB + SM_PP);
    float* PW0  = (float*)(SB + SM_PW0);

    const int tid  = threadIdx.x;
    const int lane = tid & 31;
    const int wid  = tid >> 5;
    const int bx   = blockIdx.x;
    const int e    = blockIdx.y;
    const int cnt  = g_cnt[e];
    if (bx * 128 >= cnt) return;                    // uniform exit, before any sync

    if (tid < 128) {
        int gi = bx * 128 + tid;
        int p = 0; float w0 = 0.f;
        if (gi < cnt) {
            p = g_listP[e * P_TOT + gi];
            w0 = g_listW[e * P_TOT + gi];
        }
        PP[tid]  = p;
        PW0[tid] = w0;
    }
    __syncthreads();

    for (int i = tid; i < 9 * 128; i += 256) {
        int tap = i >> 7, m = i & 127;
        int p = PP[m];
        int b = p / HWSZ, r = p - b * HWSZ;
        int h = r / 96, w = r - h * 96;
        int hh = h + tap / 3 - 1, ww = w + tap % 3 - 1;
        SPIX[i] = ((unsigned)hh < 96u && (unsigned)ww < 96u)
                      ? b * HWSZ + hh * 96 + ww : -1;
    }
    __syncthreads();

    fill_stage(tid, sb32, 0, e, SPIX);
    fill_stage(tid, sb32 + 32768u, 1, e, SPIX);

    // warp tile: m32 x n64
    const int m0 = (wid & 3) * 32;
    const int n0 = (wid >> 2) * 64;
    const int j  = lane >> 3, r8 = lane & 7;

    float acc[2][8][4];
#pragma unroll
    for (int a = 0; a < 2; ++a)
#pragma unroll
        for (int b = 0; b < 8; ++b)
#pragma unroll
            for (int c = 0; c < 4; ++c) acc[a][b][c] = 0.f;

    for (int kb = 0; kb < NKB; ++kb) {
        if (kb < NKB - 1) asm volatile("cp.async.wait_group 1;" ::: "memory");
        else              asm volatile("cp.async.wait_group 0;" ::: "memory");
        __syncthreads();
        const uint32_t aS = sb32 + (uint32_t)(kb & 1) * 32768u;
        const uint32_t bS = aS + 16384u;
#pragma unroll
        for (int ks = 0; ks < 4; ++ks) {
            uint32_t afr[2][4], bfr[4][4];
#pragma unroll
            for (int mt = 0; mt < 2; ++mt) {
                int row = m0 + mt * 16 + ((j & 1) << 3) + r8;
                int cc  = (ks << 1) + (j >> 1);
                ldm4(afr[mt], aS + row * 128 + ((cc ^ (row & 7)) << 4));
            }
#pragma unroll
            for (int np = 0; np < 4; ++np) {
                int row = n0 + np * 16 + ((j >> 1) << 3) + r8;
                int cc  = (ks << 1) + (j & 1);
                ldm4(bfr[np], bS + row * 128 + ((cc ^ (row & 7)) << 4));
            }
#pragma unroll
            for (int mt = 0; mt < 2; ++mt)
#pragma unroll
                for (int nn = 0; nn < 8; ++nn)
                    mma16816(acc[mt][nn], afr[mt], &bfr[nn >> 1][(nn & 1) * 2]);
        }
        __syncthreads();
        if (kb + 2 < NKB) fill_stage(tid, sb32 + (uint32_t)(kb & 1) * 32768u,
                                     kb + 2, e, SPIX);
    }

    // epilogue: coalesced atomics into pixel-major scratch
    const int lr = lane >> 2, lc = (lane & 3) * 2;
#pragma unroll
    for (int mt = 0; mt < 2; ++mt) {
#pragma unroll
        for (int hf = 0; hf < 2; ++hf) {
            const int row = m0 + mt * 16 + hf * 8 + lr;
            const long ob = (long)PP[row] * NCH;
            const float w0 = PW0[row];
            if (w0 != 0.f) {
#pragma unroll
                for (int nn = 0; nn < 8; ++nn) {
                    int co = n0 + nn * 8 + lc;
                    atomicAdd(&g_acc[ob + co],     w0 * acc[mt][nn][hf * 2]);
                    atomicAdd(&g_acc[ob + co + 1], w0 * acc[mt][nn][hf * 2 + 1]);
                }
            }
        }
    }
}

// ---------------- finalize: transpose scratch to NCHW + fold all biases -------------
__global__ void finalize(const float* __restrict__ expert_b,
                         const float* __restrict__ shared_b,
                         float* __restrict__ out) {
    __shared__ float t[32][33];
    __shared__ float EBS[NE * 132];
    __shared__ float SBS[NCH];
    const int b = blockIdx.z, co0 = blockIdx.y * 32, p0 = blockIdx.x * 32;
    const int tx = threadIdx.x, ty = threadIdx.y;   // (32, 8)
    const int tid = ty * 32 + tx;
    for (int i = tid; i < NE * NCH; i += 256)
        EBS[(i >> 7) * 132 + (i & 127)] = expert_b[i];
    for (int i = tid; i < NCH; i += 256) SBS[i] = shared_b[i];
#pragma unroll
    for (int j = 0; j < 32; j += 8)
        t[ty + j][tx] = g_acc[(long)(b * HWSZ + p0 + ty + j) * NCH + co0 + tx];
    __syncthreads();
    const int p = b * HWSZ + p0 + tx;
    const int s = g_sel01[p];
    const float2 w = g_w01[p];
    const float* b0 = &EBS[(s & 255) * 132];
    const float* b1 = &EBS[(s >> 8) * 132];
#pragma unroll
    for (int j = 0; j < 32; j += 8) {
        int co = co0 + ty + j;
        out[(long)(b * NCH + co) * HWSZ + p0 + tx] =
            t[tx][ty + j] + SBS[co] + w.x * b0[co] + w.y * b1[co];
    }
}

// ---------------- launch ----------------
extern "C" void kernel_launch(void* const* d_in, const int* in_sizes, int n_in,
                              void* d_out, int out_size) {
    const float* x        = (const float*)d_in[0];
    const float* gate_w   = (const float*)d_in[1];
    const float* gate_b   = (const float*)d_in[2];
    const float* expert_w = (const float*)d_in[3];
    const float* expert_b = (const float*)d_in[4];
    const float* shared_w = (const float*)d_in[5];
    const float* shared_b = (const float*)d_in[6];
    float* out = (float*)d_out;

    cudaFuncSetAttribute(conv_mma,
                         cudaFuncAttributeMaxDynamicSharedMemorySize, SMEM_BYTES);

    void* accp = nullptr;
    cudaGetSymbolAddress(&accp, g_acc);

    prep_w<<<(NE * NKB * 128 * 64 + 255) / 256, 256>>>(expert_w, shared_w);
    cudaMemsetAsync(accp, 0, (size_t)P_TOT * NCH * sizeof(float));
    gate_kernel<<<dim3(3, 12, 4), 128>>>(x, gate_w, gate_b);
    list_count<<<NPART, 1024>>>();
    list_scatter<<<dim3(NPART, NE), 1024>>>();
    conv_mma<<<dim3(P_TOT / 128, NE), 256, SMEM_BYTES>>>();
    finalize<<<dim3(HWSZ / 32, NCH / 32, 4), dim3(32, 8)>>>(expert_b, shared_b, out);
}

// round 16
// speedup vs baseline: 1.1101x; 1.1101x over previous
#include <cuda_runtime.h>
#include <cuda_fp16.h>
#include <cstdint>

#define HWSZ 9216            // 96*96
#define NCH  128
#define NE   8
#define P_TOT 36864          // 4*96*96
#define KFULL 1152           // 128*9
#define NKB   18             // K-blocks of 64, tap-major: k = tap*128 + ci
#define NPART 32
#define PPP   (P_TOT / NPART)   // 1152 pixels per part

typedef unsigned long long ull;

// ---------------- device scratch ----------------
// x transposed, CHUNK-MAJOR: [cc=16][pixel][8 halves] (16B per pixel per chunk)
__device__ __half g_xh[16 * (long)P_TOT * 8];
__device__ __half g_wh[(long)NE * NKB * 128 * 64];     // merged (We+Wsh) B tiles, fp16
__device__ float  g_acc[(long)P_TOT * NCH];            // pixel-major accumulator
__device__ int    g_sel01[P_TOT];
__device__ float2 g_w01[P_TOT];
__device__ int    g_listP[NE * P_TOT];
__device__ float  g_listW[NE * P_TOT];
__device__ int    g_cnt[NE];
__device__ int    g_pcnt[NE * NPART];

// ---------------- smem layout for conv (offsets from 1024-aligned base) -------------
#define SM_SPIX 65536        // 9*128 int
#define SM_PP   70144        // 128 int
#define SM_PW0  70656        // 128 float
#define SMEM_BYTES 72192

// ---------------- PTX helpers ----------------
__device__ __forceinline__ uint32_t smem_u32(const void* p) {
    return (uint32_t)__cvta_generic_to_shared(p);
}
__device__ __forceinline__ void cpa16(uint32_t dst, const void* src, int ssz) {
    asm volatile("cp.async.cg.shared.global [%0], [%1], 16, %2;"
                 :: "r"(dst), "l"(src), "r"(ssz) : "memory");
}
__device__ __forceinline__ void cp_commit() {
    asm volatile("cp.async.commit_group;" ::: "memory");
}
__device__ __forceinline__ void ldm4(uint32_t* r, uint32_t addr) {
    asm volatile("ldmatrix.sync.aligned.m8n8.x4.shared.b16 {%0,%1,%2,%3}, [%4];"
                 : "=r"(r[0]), "=r"(r[1]), "=r"(r[2]), "=r"(r[3]) : "r"(addr));
}
__device__ __forceinline__ void mma16816(float* d, const uint32_t* a, const uint32_t* b) {
    asm volatile("mma.sync.aligned.m16n8k16.row.col.f32.f16.f16.f32 "
                 "{%0,%1,%2,%3}, {%4,%5,%6,%7}, {%8,%9}, {%0,%1,%2,%3};"
                 : "+f"(d[0]), "+f"(d[1]), "+f"(d[2]), "+f"(d[3])
                 : "r"(a[0]), "r"(a[1]), "r"(a[2]), "r"(a[3]),
                   "r"(b[0]), "r"(b[1]));
}
__device__ __forceinline__ ull ffma2(ull a, ull b, ull c) {
    ull d;
    asm("fma.rn.f32x2 %0, %1, %2, %3;" : "=l"(d) : "l"(a), "l"(b), "l"(c));
    return d;
}
__device__ __forceinline__ ull pack2(float lo, float hi) {
    ull d;
    asm("mov.b64 %0, {%1, %2};" : "=l"(d) : "f"(lo), "f"(hi));
    return d;
}
__device__ __forceinline__ ull dup2(float x) {
    ull d;
    asm("mov.b64 %0, {%1, %1};" : "=l"(d) : "f"(x));
    return d;
}
__device__ __forceinline__ float2 unpack2(ull a) {
    float2 r;
    asm("mov.b64 {%0, %1}, %2;" : "=f"(r.x), "=f"(r.y) : "l"(a));
    return r;
}

// ---------------- prep: merged fp16 weights (We + Wsh), pre-swizzled ----------------
__global__ void prep_w(const float* __restrict__ expert_w,
                       const float* __restrict__ shared_w) {
    int idx = blockIdx.x * 256 + threadIdx.x;
    if (idx >= NE * NKB * 128 * 64) return;
    int c   = idx & 63;            // k within 64-block
    int row = (idx >> 6) & 127;    // cout
    int t2  = idx >> 13;
    int kb  = t2 % NKB;
    int e   = t2 / NKB;
    int tap = kb >> 1;
    int ci  = ((kb & 1) << 6) + c;
    float v = expert_w[(((e * NCH + row) * NCH) + ci) * 9 + tap]
            + shared_w[((row * NCH) + ci) * 9 + tap];
    int chunk = c >> 3, within = c & 7;
    int swc = chunk ^ (row & 7);                    // 16B-chunk XOR swizzle
    g_wh[(long)(e * NKB + kb) * 8192 + row * 64 + swc * 8 + within] = __float2half_rn(v);
}

// ---------------- gate (f32x2, 2 pixels/thread) + fused packed x_t emission ---------
// block: 128 threads, tile 32 wide x 8 tall. grid (3, 12, 4).
__global__ __launch_bounds__(128) void gate_kernel(
    const float* __restrict__ x, const float* __restrict__ gate_w,
    const float* __restrict__ gate_bias)
{
    __shared__ float xt[8 * 10 * 34];    // 8 ci x (8+2 halo rows) x (32+2 halo cols)
    __shared__ float gwS[NE * 72];       // current chunk: [e][ci*9+t]
    const int tid = threadIdx.x;
    const int tx = tid & 15, ty = tid >> 4;   // pair at w=2tx, row ty
    const int w0 = blockIdx.x * 32, h0 = blockIdx.y * 8, b = blockIdx.z;
    const float* xb = x + (long)b * (NCH * HWSZ);

    ull acc2[NE];
#pragma unroll
    for (int e = 0; e < NE; ++e) acc2[e] = 0ull;

    for (int cc = 0; cc < 16; ++cc) {            // 16 chunks of 8 ci
        __syncthreads();
        for (int i = tid; i < NE * 72; i += 128)
            gwS[i] = gate_w[(i / 72) * KFULL + cc * 72 + (i % 72)];
        for (int i = tid; i < 8 * 340; i += 128) {
            int ci = i / 340; int r = i - ci * 340;
            int ly = r / 34;  int lx = r - ly * 34;
            int gh = h0 + ly - 1, gw = w0 + lx - 1;
            float v = 0.f;
            if ((unsigned)gh < 96u && (unsigned)gw < 96u)
                v = xb[(cc * 8 + ci) * HWSZ + gh * 96 + gw];
            xt[i] = v;
        }
        __syncthreads();
        // emit packed fp16 x_t: one uint4 (8 halves) per pixel, coalesced
        for (int i = tid; i < 256; i += 128) {
            int row = i >> 5, col = i & 31;
            union { __half h[8]; uint4 v; } u;
#pragma unroll
            for (int ci = 0; ci < 8; ++ci)
                u.h[ci] = __float2half_rn(xt[ci * 340 + (row + 1) * 34 + col + 1]);
            long p = (long)b * HWSZ + (h0 + row) * 96 + w0 + col;
            *(uint4*)&g_xh[((long)cc * P_TOT + p) * 8] = u.v;
        }
        // packed-pair compute
#pragma unroll
        for (int ci = 0; ci < 8; ++ci) {
#pragma unroll
            for (int r = 0; r < 3; ++r) {
                const float* rowp = &xt[ci * 340 + (ty + r) * 34 + 2 * tx];
                float2 a = *(const float2*)rowp;
                float2 bv = *(const float2*)(rowp + 2);
                ull p0 = pack2(a.x, a.y);
                ull p1 = pack2(a.y, bv.x);
                ull p2 = pack2(bv.x, bv.y);
#pragma unroll
                for (int e = 0; e < NE; ++e) {
                    const float* wp = &gwS[e * 72 + ci * 9 + r * 3];
                    acc2[e] = ffma2(p0, dup2(wp[0]), acc2[e]);
                    acc2[e] = ffma2(p1, dup2(wp[1]), acc2[e]);
                    acc2[e] = ffma2(p2, dup2(wp[2]), acc2[e]);
                }
            }
        }
    }

    float sc[2][NE];
#pragma unroll
    for (int e = 0; e < NE; ++e) {
        float2 v = unpack2(acc2[e]);
        sc[0][e] = v.x; sc[1][e] = v.y;
    }
#pragma unroll
    for (int jx = 0; jx < 2; ++jx) {
        float s[NE];
        float v0 = -1e30f, v1 = -1e30f; int i0 = 0, i1 = 1;
#pragma unroll
        for (int e = 0; e < NE; ++e) {
            float sv = 1.f / (1.f + expf(-sc[jx][e]));
            s[e] = sv;
            float bv = sv + gate_bias[e];
            if (bv > v0)      { v1 = v0; i1 = i0; v0 = bv; i0 = e; }
            else if (bv > v1) { v1 = bv; i1 = e; }
        }
        float s0 = s[i0], s1 = s[i1];
        float mx = fmaxf(s0, s1);
        float e0 = expf(s0 - mx), e1 = expf(s1 - mx);
        float inv = 1.f / (e0 + e1);
        const int p = b * HWSZ + (h0 + ty) * 96 + w0 + 2 * tx + jx;
        g_sel01[p] = i0 | (i1 << 8);
        g_w01[p]   = make_float2(e0 * inv, e1 * inv);
    }
}

// ---------------- parallel deterministic list build --------------------------------
__global__ __launch_bounds__(1024) void list_count() {
    __shared__ int wc[32][8];
    const int part = blockIdx.x;
    const int tid = threadIdx.x, lane = tid & 31, wrp = tid >> 5;
    int cnt = 0;
#pragma unroll
    for (int seg = 0; seg < 2; ++seg) {
        int off = seg * 1024 + tid;
        bool valid = off < PPP;
        int s01 = valid ? g_sel01[part * PPP + off] : 0x0F0F;
#pragma unroll
        for (int e = 0; e < NE; ++e) {
            unsigned m0 = __ballot_sync(0xFFFFFFFFu, (s01 & 255) == e);
            unsigned m1 = __ballot_sync(0xFFFFFFFFu, (s01 >> 8) == e);
            if (lane == e) cnt += __popc(m0) + __popc(m1);
        }
    }
    if (lane < 8) wc[wrp][lane] = cnt;
    __syncthreads();
    if (tid < 8) {
        int a = 0;
#pragma unroll
        for (int w2 = 0; w2 < 32; ++w2) a += wc[w2][tid];
        g_pcnt[tid * NPART + part] = a;
    }
}

__global__ __launch_bounds__(1024) void list_scatter() {
    __shared__ int wsum[32];
    __shared__ int woff[33];
    __shared__ int sbase;
    const int part = blockIdx.x, e = blockIdx.y;
    const int tid = threadIdx.x, lane = tid & 31, wrp = tid >> 5;
    if (tid == 0) {
        int a = 0, tot = 0;
#pragma unroll
        for (int p2 = 0; p2 < NPART; ++p2) {
            int c = g_pcnt[e * NPART + p2];
            if (p2 < part) a += c;
            tot += c;
        }
        sbase = a;
        if (part == 0) g_cnt[e] = tot;
    }
    __syncthreads();
    int base = sbase;
#pragma unroll
    for (int seg = 0; seg < 2; ++seg) {
        int off = seg * 1024 + tid;
        bool valid = off < PPP;
        int p = part * PPP + off;
        int s01 = valid ? g_sel01[p] : 0x0F0F;
        bool f0 = ((s01 & 255) == e), f1 = ((s01 >> 8) == e);
        bool f = f0 || f1;
        unsigned msk = __ballot_sync(0xFFFFFFFFu, f);
        if (lane == 0) wsum[wrp] = __popc(msk);
        __syncthreads();
        if (tid == 0) {
            int a = 0;
#pragma unroll
            for (int w2 = 0; w2 < 32; ++w2) { woff[w2] = a; a += wsum[w2]; }
            woff[32] = a;
        }
        __syncthreads();
        if (f) {
            float2 ww = g_w01[p];
            int pos = base + woff[wrp] + __popc(msk & ((1u << lane) - 1u));
            g_listP[e * P_TOT + pos] = p;
            g_listW[e * P_TOT + pos] = f0 ? ww.x : ww.y;
        }
        base += woff[32];
        __syncthreads();
    }
}

// ---------------- stage fill: gathered A (chunk-major, coalesced) + B slab ----------
__device__ __forceinline__ void fill_stage(int tid, uint32_t bb, int kb, int e,
                                           const int* SPIX) {
    const int tap = kb >> 1;
    const int ch0 = (kb & 1) << 3;                  // first 8-ci chunk of this K-block
    const char* xs = (const char*)g_xh;
    for (int i = tid; i < 1024; i += 256) {         // consecutive lanes -> consecutive rows
        int cc = i >> 7, r = i & 127;
        int sp = SPIX[tap * 128 + r];
        uint32_t dst = bb + (uint32_t)(r * 128 + ((cc ^ (r & 7)) << 4));
        const char* src = xs + ((long)(ch0 + cc) * P_TOT + (sp < 0 ? 0 : sp)) * 16;
        cpa16(dst, src, sp < 0 ? 0 : 16);
    }
    const char* ws = (const char*)g_wh;
    const long wb = (long)(e * NKB + kb) * 16384;
    for (int i = tid; i < 1024; i += 256)           // B: plain slab copy
        cpa16(bb + 16384u + (uint32_t)i * 16, ws + wb + (long)i * 16, 16);
    cp_commit();
}

// ---------------- mma.sync conv: one (expert, 128-pixel, 128-cout) tile per CTA -----
__global__ __launch_bounds__(256, 2) void conv_mma()
{
    extern __shared__ char dsm[];
    char* SB = (char*)(((uintptr_t)dsm + 1023) & ~(uintptr_t)1023);
    const uint32_t sb32 = smem_u32(SB);

    int*   SPIX = (int*)(SB + SM_SPIX);
    int*   PP   = (int*)(SB + SM_PP);
    float* PW0  = (float*)(SB + SM_PW0);

    const int tid  = threadIdx.x;
    const int lane = tid & 31;
    const int wid  = tid >> 5;
    const int bx   = blockIdx.x;
    const int e    = blockIdx.y;
    const int cnt  = g_cnt[e];
    if (bx * 128 >= cnt) return;                    // uniform exit, before any sync

    if (tid < 128) {
        int gi = bx * 128 + tid;
        int p = 0; float w0 = 0.f;
        if (gi < cnt) {
            p = g_listP[e * P_TOT + gi];
            w0 = g_listW[e * P_TOT + gi];
        }
        PP[tid]  = p;
        PW0[tid] = w0;
    }
    __syncthreads();

    for (int i = tid; i < 9 * 128; i += 256) {
        int tap = i >> 7, m = i & 127;
        int p = PP[m];
        int b = p / HWSZ, r = p - b * HWSZ;
        int h = r / 96, w = r - h * 96;
        int hh = h + tap / 3 - 1, ww = w + tap % 3 - 1;
        SPIX[i] = ((unsigned)hh < 96u && (unsigned)ww < 96u)
                      ? b * HWSZ + hh * 96 + ww : -1;
    }
    __syncthreads();

    fill_stage(tid, sb32, 0, e, SPIX);
    fill_stage(tid, sb32 + 32768u, 1, e, SPIX);

    // warp tile: m32 x n64
    const int m0 = (wid & 3) * 32;
    const int n0 = (wid >> 2) * 64;
    const int j  = lane >> 3, r8 = lane & 7;

    float acc[2][8][4];
#pragma unroll
    for (int a = 0; a < 2; ++a)
#pragma unroll
        for (int b = 0; b < 8; ++b)
#pragma unroll
            for (int c = 0; c < 4; ++c) acc[a][b][c] = 0.f;

    for (int kb = 0; kb < NKB; ++kb) {
        if (kb < NKB - 1) asm volatile("cp.async.wait_group 1;" ::: "memory");
        else              asm volatile("cp.async.wait_group 0;" ::: "memory");
        __syncthreads();
        const uint32_t aS = sb32 + (uint32_t)(kb & 1) * 32768u;
        const uint32_t bS = aS + 16384u;
#pragma unroll
        for (int ks = 0; ks < 4; ++ks) {
            uint32_t afr[2][4], bfr[4][4];
#pragma unroll
            for (int mt = 0; mt < 2; ++mt) {
                int row = m0 + mt * 16 + ((j & 1) << 3) + r8;
                int cc  = (ks << 1) + (j >> 1);
                ldm4(afr[mt], aS + row * 128 + ((cc ^ (row & 7)) << 4));
            }
#pragma unroll
            for (int np = 0; np < 4; ++np) {
                int row = n0 + np * 16 + ((j >> 1) << 3) + r8;
                int cc  = (ks << 1) + (j & 1);
                ldm4(bfr[np], bS + row * 128 + ((cc ^ (row & 7)) << 4));
            }
#pragma unroll
            for (int mt = 0; mt < 2; ++mt)
#pragma unroll
                for (int nn = 0; nn < 8; ++nn)
                    mma16816(acc[mt][nn], afr[mt], &bfr[nn >> 1][(nn & 1) * 2]);
        }
        __syncthreads();
        if (kb + 2 < NKB) fill_stage(tid, sb32 + (uint32_t)(kb & 1) * 32768u,
                                     kb + 2, e, SPIX);
    }

    // epilogue: coalesced atomics into pixel-major scratch
    const int lr = lane >> 2, lc = (lane & 3) * 2;
#pragma unroll
    for (int mt = 0; mt < 2; ++mt) {
#pragma unroll
        for (int hf = 0; hf < 2; ++hf) {
            const int row = m0 + mt * 16 + hf * 8 + lr;
            const long ob = (long)PP[row] * NCH;
            const float w0 = PW0[row];
            if (w0 != 0.f) {
#pragma unroll
                for (int nn = 0; nn < 8; ++nn) {
                    int co = n0 + nn * 8 + lc;
                    atomicAdd(&g_acc[ob + co],     w0 * acc[mt][nn][hf * 2]);
                    atomicAdd(&g_acc[ob + co + 1], w0 * acc[mt][nn][hf * 2 + 1]);
                }
            }
        }
    }
}

// ---------------- finalize: transpose scratch to NCHW + fold all biases -------------
__global__ void finalize(const float* __restrict__ expert_b,
                         const float* __restrict__ shared_b,
                         float* __restrict__ out) {
    __shared__ float t[32][33];
    __shared__ float EBS[NE * 132];
    __shared__ float SBS[NCH];
    const int b = blockIdx.z, co0 = blockIdx.y * 32, p0 = blockIdx.x * 32;
    const int tx = threadIdx.x, ty = threadIdx.y;   // (32, 8)
    const int tid = ty * 32 + tx;
    for (int i = tid; i < NE * NCH; i += 256)
        EBS[(i >> 7) * 132 + (i & 127)] = expert_b[i];
    for (int i = tid; i < NCH; i += 256) SBS[i] = shared_b[i];
#pragma unroll
    for (int j = 0; j < 32; j += 8)
        t[ty + j][tx] = g_acc[(long)(b * HWSZ + p0 + ty + j) * NCH + co0 + tx];
    __syncthreads();
    const int p = b * HWSZ + p0 + tx;
    const int s = g_sel01[p];
    const float2 w = g_w01[p];
    const float* b0 = &EBS[(s & 255) * 132];
    const float* b1 = &EBS[(s >> 8) * 132];
#pragma unroll
    for (int j = 0; j < 32; j += 8) {
        int co = co0 + ty + j;
        out[(long)(b * NCH + co) * HWSZ + p0 + tx] =
            t[tx][ty + j] + SBS[co] + w.x * b0[co] + w.y * b1[co];
    }
}

// ---------------- launch ----------------
extern "C" void kernel_launch(void* const* d_in, const int* in_sizes, int n_in,
                              void* d_out, int out_size) {
    const float* x        = (const float*)d_in[0];
    const float* gate_w   = (const float*)d_in[1];
    const float* gate_b   = (const float*)d_in[2];
    const float* expert_w = (const float*)d_in[3];
    const float* expert_b = (const float*)d_in[4];
    const float* shared_w = (const float*)d_in[5];
    const float* shared_b = (const float*)d_in[6];
    float* out = (float*)d_out;

    cudaFuncSetAttribute(conv_mma,
                         cudaFuncAttributeMaxDynamicSharedMemorySize, SMEM_BYTES);

    void* accp = nullptr;
    cudaGetSymbolAddress(&accp, g_acc);

    prep_w<<<(NE * NKB * 128 * 64 + 255) / 256, 256>>>(expert_w, shared_w);
    cudaMemsetAsync(accp, 0, (size_t)P_TOT * NCH * sizeof(float));
    gate_kernel<<<dim3(3, 12, 4), 128>>>(x, gate_w, gate_b);
    list_count<<<NPART, 1024>>>();
    list_scatter<<<dim3(NPART, NE), 1024>>>();
    conv_mma<<<dim3(P_TOT / 128, NE), 256, SMEM_BYTES>>>();
    finalize<<<dim3(HWSZ / 32, NCH / 32, 4), dim3(32, 8)>>>(expert_b, shared_b, out);
}